// round 15
// baseline (speedup 1.0000x reference)
#include <cuda_runtime.h>
#include <cuda_fp16.h>
#include <cstdint>

// ---------------------------------------------------------------------------
// GQA causal flash attention (prefill), fp16 mma.sync m16n8k16 + ldmatrix,
// producer/consumer warp-specialized with mbarrier ring (no __syncthreads in
// the mainloop -> consumer warps drift and overlap phases).
// S=2048, 32 Q heads / 8 KV heads, D=128, fp32 in/out.
// Br=128 x Bc=64; warps 0-7 consumers (16-row strips, Q in registers);
// warp 8 producer stages K+V tiles into a 3-deep smem ring via cp.async.
// K/V pre-converted to fp16 in gmem scratch by a tiny pre-kernel.
// ---------------------------------------------------------------------------

#define NUM_HEADS 32
#define HEAD_DIM  128
#define QSTRIDE   4096
#define KSTRIDE   1024
#define BR 128
#define BC 64
#define NTHREADS 288        // 8 consumer warps + 1 producer warp
#define NBUF 3

// smem ring: buffer b at b*32KB = [K 16KB][V 16KB]; mbarriers after.
#define TILEB   32768u
#define MB_OFF  98304u      // 3*32768
#define SMEM_BYTES (98304 + 64)

__device__ __half d_Kh[2048 * 1024];
__device__ __half d_Vh[2048 * 1024];

static __device__ __forceinline__ uint32_t smem_u32(const void* p) {
    uint32_t a;
    asm("{ .reg .u64 t; cvta.to.shared.u64 t, %1; cvt.u32.u64 %0, t; }" : "=r"(a) : "l"(p));
    return a;
}
static __device__ __forceinline__ float ex2f(float x) {
    float y; asm("ex2.approx.ftz.f32 %0, %1;" : "=f"(y) : "f"(x)); return y;
}
static __device__ __forceinline__ unsigned packh2(float lo, float hi) {
    __half2 h = __floats2half2_rn(lo, hi);
    return *reinterpret_cast<unsigned*>(&h);
}
static __device__ __forceinline__ void mma_f16(float* c, const unsigned* a,
                                               unsigned b0, unsigned b1) {
    asm("mma.sync.aligned.m16n8k16.row.col.f32.f16.f16.f32 "
        "{%0,%1,%2,%3}, {%4,%5,%6,%7}, {%8,%9}, {%0,%1,%2,%3};"
        : "+f"(c[0]), "+f"(c[1]), "+f"(c[2]), "+f"(c[3])
        : "r"(a[0]), "r"(a[1]), "r"(a[2]), "r"(a[3]), "r"(b0), "r"(b1));
}
static __device__ __forceinline__ void ldsm4(unsigned& r0, unsigned& r1,
                                             unsigned& r2, unsigned& r3, uint32_t addr) {
    asm volatile("ldmatrix.sync.aligned.m8n8.x4.shared.b16 {%0,%1,%2,%3}, [%4];"
                 : "=r"(r0), "=r"(r1), "=r"(r2), "=r"(r3) : "r"(addr));
}
static __device__ __forceinline__ void ldsm4t(unsigned& r0, unsigned& r1,
                                              unsigned& r2, unsigned& r3, uint32_t addr) {
    asm volatile("ldmatrix.sync.aligned.m8n8.x4.trans.shared.b16 {%0,%1,%2,%3}, [%4];"
                 : "=r"(r0), "=r"(r1), "=r"(r2), "=r"(r3) : "r"(addr));
}
static __device__ __forceinline__ void cpa16(uint32_t dst, const void* src) {
    asm volatile("cp.async.cg.shared.global [%0], [%1], 16;"
                 :: "r"(dst), "l"(__cvta_generic_to_global(src)) : "memory");
}
#define CP_COMMIT()  asm volatile("cp.async.commit_group;" ::: "memory")
#define CP_WAITALL() asm volatile("cp.async.wait_group 0;" ::: "memory")

static __device__ __forceinline__ void mbar_init(uint32_t a, uint32_t cnt) {
    asm volatile("mbarrier.init.shared.b64 [%0], %1;" :: "r"(a), "r"(cnt) : "memory");
}
static __device__ __forceinline__ void mbar_arrive(uint32_t a) {
    asm volatile("mbarrier.arrive.shared.b64 _, [%0];" :: "r"(a) : "memory");
}
static __device__ __forceinline__ void mbar_wait(uint32_t a, uint32_t parity) {
    asm volatile(
        "{\n\t.reg .pred P;\n\tW%=:\n\t"
        "mbarrier.try_wait.parity.shared.b64 P, [%0], %1;\n\t"
        "@!P bra W%=;\n\t}" :: "r"(a), "r"(parity) : "memory");
}

// ---- pre-pass: fp32 -> fp16 for K and V ----
__global__ void __launch_bounds__(256, 4)
cvt_kv(const float* __restrict__ K, const float* __restrict__ V)
{
    size_t i = ((size_t)blockIdx.x * 256 + threadIdx.x) * 8;
    float4 a = *reinterpret_cast<const float4*>(K + i);
    float4 b = *reinterpret_cast<const float4*>(K + i + 4);
    __half2 h0 = __floats2half2_rn(a.x, a.y), h1 = __floats2half2_rn(a.z, a.w);
    __half2 h2 = __floats2half2_rn(b.x, b.y), h3 = __floats2half2_rn(b.z, b.w);
    uint4 o;
    o.x = *reinterpret_cast<unsigned*>(&h0); o.y = *reinterpret_cast<unsigned*>(&h1);
    o.z = *reinterpret_cast<unsigned*>(&h2); o.w = *reinterpret_cast<unsigned*>(&h3);
    *reinterpret_cast<uint4*>(d_Kh + i) = o;
    a = *reinterpret_cast<const float4*>(V + i);
    b = *reinterpret_cast<const float4*>(V + i + 4);
    h0 = __floats2half2_rn(a.x, a.y); h1 = __floats2half2_rn(a.z, a.w);
    h2 = __floats2half2_rn(b.x, b.y); h3 = __floats2half2_rn(b.z, b.w);
    o.x = *reinterpret_cast<unsigned*>(&h0); o.y = *reinterpret_cast<unsigned*>(&h1);
    o.z = *reinterpret_cast<unsigned*>(&h2); o.w = *reinterpret_cast<unsigned*>(&h3);
    *reinterpret_cast<uint4*>(d_Vh + i) = o;
}

__global__ void __launch_bounds__(NTHREADS, 1)
fa_f16_v8(const float* __restrict__ Q, float* __restrict__ O)
{
    extern __shared__ char sm[];
    const uint32_t sb = smem_u32(sm);

    const int iq   = (int)gridDim.x - 1 - (int)blockIdx.x;   // longest first
    const int h    = blockIdx.y;
    const int g    = h >> 2;
    const int tid  = threadIdx.x;
    const int w    = tid >> 5;
    const int lane = tid & 31;
    const int jend = 2 * iq + 1;

    // mbarriers: full[b] (count 1, producer), empty[b] (count 8, consumers)
    if (tid == 0) {
        #pragma unroll
        for (int b = 0; b < NBUF; ++b) {
            mbar_init(sb + MB_OFF + b * 8, 1);
            mbar_init(sb + MB_OFF + 24 + b * 8, 8);
        }
    }
    __syncthreads();

    if (w == 8) {
        // ================= producer warp =================
        for (int t = 0; t <= jend; ++t) {
            const int b   = t % NBUF;
            const int cyc = t / NBUF;
            if (t >= NBUF)
                mbar_wait(sb + MB_OFF + 24 + b * 8, (cyc - 1) & 1);
            const __half* kg = d_Kh + (size_t)t * BC * KSTRIDE + g * 128;
            const __half* vg = d_Vh + (size_t)t * BC * KSTRIDE + g * 128;
            const uint32_t kd = sb + (uint32_t)b * TILEB;
            const uint32_t vd = kd + 16384u;
            #pragma unroll 8
            for (int i = 0; i < 32; ++i) {
                int idx = lane + i * 32;
                int r = idx >> 4, c16 = idx & 15;
                uint32_t dst = (uint32_t)(r * 256 + ((c16 ^ (r & 7)) << 4));
                cpa16(kd + dst, kg + (size_t)r * KSTRIDE + c16 * 8);
                cpa16(vd + dst, vg + (size_t)r * KSTRIDE + c16 * 8);
            }
            CP_COMMIT();
            CP_WAITALL();
            __syncwarp();
            if (lane == 0) mbar_arrive(sb + MB_OFF + b * 8);
        }
        return;
    }

    // ================= consumer warps 0..7 =================
    const int gid  = lane >> 2;
    const int t4   = lane & 3;
    const int strip  = w * 16;
    const int qrow0  = iq * BR;
    const int row0   = qrow0 + strip + gid;
    const int row1   = row0 + 8;
    const int maxrow = qrow0 + strip + 15;

    // ldmatrix per-lane address pieces
    const int rin = lane & 7;
    const int khi = (lane >> 3) & 1;
    const int qhi = (lane >> 4) & 1;
    const uint32_t g1base = (uint32_t)((qhi * 8 + rin) * 256);
    const uint32_t g2base = (uint32_t)((khi * 8 + rin) * 256);

    // ---- Q fragments in registers (fp16, pre-scaled by scale*log2(e)) ----
    unsigned aq[8][4];
    {
        const float* q0 = Q + (size_t)row0 * QSTRIDE + h * HEAD_DIM;
        const float* q1 = q0 + (size_t)8 * QSTRIDE;
        const float sc = (float)(0.08838834764831845 * 1.4426950408889634);
        #pragma unroll
        for (int kc = 0; kc < 8; ++kc) {
            int c = kc * 16 + 2 * t4;
            aq[kc][0] = packh2(q0[c] * sc,     q0[c + 1] * sc);
            aq[kc][1] = packh2(q1[c] * sc,     q1[c + 1] * sc);
            aq[kc][2] = packh2(q0[c + 8] * sc, q0[c + 9] * sc);
            aq[kc][3] = packh2(q1[c + 8] * sc, q1[c + 9] * sc);
        }
    }

    float m0 = -1e30f, m1 = -1e30f, l0 = 0.f, l1 = 0.f;
    float o[16][4];
    #pragma unroll
    for (int nt = 0; nt < 16; ++nt)
        o[nt][0] = o[nt][1] = o[nt][2] = o[nt][3] = 0.f;

    for (int j = 0; j <= jend; ++j) {
        const int b  = j % NBUF;
        const int ph = (j / NBUF) & 1;
        mbar_wait(sb + MB_OFF + b * 8, ph);       // tile j staged

        const uint32_t kb = sb + (uint32_t)b * TILEB;
        const uint32_t vb = kb + 16384u;

        const int d = maxrow - BC * j;
        if (d >= 0) {
            // ---- GEMM1: S = Q @ K^T ----
            float s[8][4];
            #pragma unroll
            for (int nt = 0; nt < 8; ++nt)
                s[nt][0] = s[nt][1] = s[nt][2] = s[nt][3] = 0.f;

            #pragma unroll
            for (int kc = 0; kc < 8; ++kc) {
                const int kch = kc * 2 + khi;
                #pragma unroll
                for (int ntp = 0; ntp < 4; ++ntp) {
                    if (16 * ntp <= d) {
                        unsigned b0, b1, b2, b3;
                        ldsm4(b0, b1, b2, b3,
                              kb + g1base + (uint32_t)(ntp * 4096) +
                              (uint32_t)(((kch ^ rin) & 15) << 4));
                        mma_f16(s[2 * ntp],     aq[kc], b0, b1);
                        mma_f16(s[2 * ntp + 1], aq[kc], b2, b3);
                    }
                }
            }

            // ---- mask + online softmax (log2 domain) ----
            const bool diag = (j >= 2 * iq);
            float mx0 = -1e30f, mx1 = -1e30f;
            #pragma unroll
            for (int nt = 0; nt < 8; ++nt) {
                if (diag) {
                    int col = j * BC + nt * 8 + 2 * t4;
                    if (col     > row0) s[nt][0] = -1e30f;
                    if (col + 1 > row0) s[nt][1] = -1e30f;
                    if (col     > row1) s[nt][2] = -1e30f;
                    if (col + 1 > row1) s[nt][3] = -1e30f;
                }
                mx0 = fmaxf(mx0, fmaxf(s[nt][0], s[nt][1]));
                mx1 = fmaxf(mx1, fmaxf(s[nt][2], s[nt][3]));
            }
            mx0 = fmaxf(mx0, __shfl_xor_sync(0xffffffffu, mx0, 1));
            mx0 = fmaxf(mx0, __shfl_xor_sync(0xffffffffu, mx0, 2));
            mx1 = fmaxf(mx1, __shfl_xor_sync(0xffffffffu, mx1, 1));
            mx1 = fmaxf(mx1, __shfl_xor_sync(0xffffffffu, mx1, 2));

            const float nm0 = fmaxf(m0, mx0);
            const float nm1 = fmaxf(m1, mx1);
            const float cf0 = ex2f(m0 - nm0);
            const float cf1 = ex2f(m1 - nm1);
            m0 = nm0; m1 = nm1;

            float rs0 = 0.f, rs1 = 0.f;
            #pragma unroll
            for (int nt = 0; nt < 8; ++nt) {
                float p0 = ex2f(s[nt][0] - m0);
                float p1 = ex2f(s[nt][1] - m0);
                float p2 = ex2f(s[nt][2] - m1);
                float p3 = ex2f(s[nt][3] - m1);
                rs0 += p0 + p1; rs1 += p2 + p3;
                s[nt][0] = p0; s[nt][1] = p1; s[nt][2] = p2; s[nt][3] = p3;
            }
            l0 = l0 * cf0 + rs0;      // per-thread partial; quad-reduced in epilogue
            l1 = l1 * cf1 + rs1;

            #pragma unroll
            for (int nt = 0; nt < 16; ++nt) {
                o[nt][0] *= cf0; o[nt][1] *= cf0;
                o[nt][2] *= cf1; o[nt][3] *= cf1;
            }

            // ---- GEMM2: O += P @ V ----
            #pragma unroll
            for (int kc2 = 0; kc2 < 4; ++kc2) {
                if (16 * kc2 <= d) {
                    unsigned a[4];
                    a[0] = packh2(s[2 * kc2][0],     s[2 * kc2][1]);
                    a[1] = packh2(s[2 * kc2][2],     s[2 * kc2][3]);
                    a[2] = packh2(s[2 * kc2 + 1][0], s[2 * kc2 + 1][1]);
                    a[3] = packh2(s[2 * kc2 + 1][2], s[2 * kc2 + 1][3]);
                    #pragma unroll
                    for (int ntp2 = 0; ntp2 < 8; ++ntp2) {
                        unsigned b0, b1, b2, b3;
                        ldsm4t(b0, b1, b2, b3,
                               vb + g2base + (uint32_t)(kc2 * 4096) +
                               (uint32_t)((((2 * ntp2 + qhi) ^ rin) & 15) << 4));
                        mma_f16(o[2 * ntp2],     a, b0, b1);
                        mma_f16(o[2 * ntp2 + 1], a, b2, b3);
                    }
                }
            }
        }

        __syncwarp();
        if (lane == 0) mbar_arrive(sb + MB_OFF + 24 + b * 8);   // release buffer
    }

    // ---- epilogue: reduce l across quad, normalize, store ----
    l0 += __shfl_xor_sync(0xffffffffu, l0, 1);
    l0 += __shfl_xor_sync(0xffffffffu, l0, 2);
    l1 += __shfl_xor_sync(0xffffffffu, l1, 1);
    l1 += __shfl_xor_sync(0xffffffffu, l1, 2);
    const float inv0 = 1.f / l0;
    const float inv1 = 1.f / l1;
    float* ob0 = O + (size_t)row0 * QSTRIDE + h * HEAD_DIM + 2 * t4;
    float* ob1 = ob0 + (size_t)8 * QSTRIDE;
    #pragma unroll
    for (int nt = 0; nt < 16; ++nt) {
        float2 x0 = make_float2(o[nt][0] * inv0, o[nt][1] * inv0);
        float2 x1 = make_float2(o[nt][2] * inv1, o[nt][3] * inv1);
        *reinterpret_cast<float2*>(ob0 + nt * 8) = x0;
        *reinterpret_cast<float2*>(ob1 + nt * 8) = x1;
    }
}

extern "C" void kernel_launch(void* const* d_in, const int* in_sizes, int n_in,
                              void* d_out, int out_size)
{
    const float* Q = (const float*)d_in[0];
    const float* K = (const float*)d_in[1];
    const float* V = (const float*)d_in[2];
    float* O = (float*)d_out;

    cvt_kv<<<1024, 256>>>(K, V);

    cudaFuncSetAttribute(fa_f16_v8,
                         cudaFuncAttributeMaxDynamicSharedMemorySize, SMEM_BYTES);
    dim3 grid(2048 / BR, NUM_HEADS);
    fa_f16_v8<<<grid, NTHREADS, SMEM_BYTES>>>(Q, O);
}

// round 17
// speedup vs baseline: 1.0763x; 1.0763x over previous
#include <cuda_runtime.h>
#include <cuda_fp16.h>
#include <cstdint>

// ---------------------------------------------------------------------------
// GQA causal flash attention (prefill), fp16 mma.sync m16n8k16 + ldmatrix.
// S=2048, 32 Q heads / 8 KV heads, D=128, fp32 in/out.
// v5 decomposition (8 warps, Br=128, warp = 16-row strip, Q frags in regs,
// K/V fp16 gmem scratch) with: 128-row kv chunks per stage (2 sub-tiles per
// barrier pair), deferred l-reduction, half2-packed max shuffles, and
// vote-skipped O rescale.
// ---------------------------------------------------------------------------

#define NUM_HEADS 32
#define HEAD_DIM  128
#define QSTRIDE   4096
#define KSTRIDE   1024
#define BR 128
#define NTHREADS 256

// smem: [K0 32KB][K1 32KB][V0 32KB][V1 32KB] (fp16 128x128 chunks, 256B rows)
#define SM_V0 65536u
#define SMEM_BYTES 131072

__device__ __half d_Kh[2048 * 1024];
__device__ __half d_Vh[2048 * 1024];

static __device__ __forceinline__ uint32_t smem_u32(const void* p) {
    uint32_t a;
    asm("{ .reg .u64 t; cvta.to.shared.u64 t, %1; cvt.u32.u64 %0, t; }" : "=r"(a) : "l"(p));
    return a;
}
static __device__ __forceinline__ float ex2f(float x) {
    float y; asm("ex2.approx.ftz.f32 %0, %1;" : "=f"(y) : "f"(x)); return y;
}
static __device__ __forceinline__ unsigned packh2(float lo, float hi) {
    __half2 h = __floats2half2_rn(lo, hi);
    return *reinterpret_cast<unsigned*>(&h);
}
static __device__ __forceinline__ void mma_f16(float* c, const unsigned* a,
                                               unsigned b0, unsigned b1) {
    asm("mma.sync.aligned.m16n8k16.row.col.f32.f16.f16.f32 "
        "{%0,%1,%2,%3}, {%4,%5,%6,%7}, {%8,%9}, {%0,%1,%2,%3};"
        : "+f"(c[0]), "+f"(c[1]), "+f"(c[2]), "+f"(c[3])
        : "r"(a[0]), "r"(a[1]), "r"(a[2]), "r"(a[3]), "r"(b0), "r"(b1));
}
static __device__ __forceinline__ void ldsm4(unsigned& r0, unsigned& r1,
                                             unsigned& r2, unsigned& r3, uint32_t addr) {
    asm volatile("ldmatrix.sync.aligned.m8n8.x4.shared.b16 {%0,%1,%2,%3}, [%4];"
                 : "=r"(r0), "=r"(r1), "=r"(r2), "=r"(r3) : "r"(addr));
}
static __device__ __forceinline__ void ldsm4t(unsigned& r0, unsigned& r1,
                                              unsigned& r2, unsigned& r3, uint32_t addr) {
    asm volatile("ldmatrix.sync.aligned.m8n8.x4.trans.shared.b16 {%0,%1,%2,%3}, [%4];"
                 : "=r"(r0), "=r"(r1), "=r"(r2), "=r"(r3) : "r"(addr));
}
static __device__ __forceinline__ void cpa16(uint32_t dst, const void* src) {
    asm volatile("cp.async.cg.shared.global [%0], [%1], 16;"
                 :: "r"(dst), "l"(__cvta_generic_to_global(src)) : "memory");
}
#define CP_COMMIT() asm volatile("cp.async.commit_group;" ::: "memory")
#define CP_WAIT1()  asm volatile("cp.async.wait_group 1;" ::: "memory")
#define CP_WAIT0()  asm volatile("cp.async.wait_group 0;" ::: "memory")

// ---- pre-pass: fp32 -> fp16 for K and V ----
__global__ void __launch_bounds__(256, 4)
cvt_kv(const float* __restrict__ K, const float* __restrict__ V)
{
    size_t i = ((size_t)blockIdx.x * 256 + threadIdx.x) * 8;
    float4 a = *reinterpret_cast<const float4*>(K + i);
    float4 b = *reinterpret_cast<const float4*>(K + i + 4);
    __half2 h0 = __floats2half2_rn(a.x, a.y), h1 = __floats2half2_rn(a.z, a.w);
    __half2 h2 = __floats2half2_rn(b.x, b.y), h3 = __floats2half2_rn(b.z, b.w);
    uint4 o;
    o.x = *reinterpret_cast<unsigned*>(&h0); o.y = *reinterpret_cast<unsigned*>(&h1);
    o.z = *reinterpret_cast<unsigned*>(&h2); o.w = *reinterpret_cast<unsigned*>(&h3);
    *reinterpret_cast<uint4*>(d_Kh + i) = o;
    a = *reinterpret_cast<const float4*>(V + i);
    b = *reinterpret_cast<const float4*>(V + i + 4);
    h0 = __floats2half2_rn(a.x, a.y); h1 = __floats2half2_rn(a.z, a.w);
    h2 = __floats2half2_rn(b.x, b.y); h3 = __floats2half2_rn(b.z, b.w);
    o.x = *reinterpret_cast<unsigned*>(&h0); o.y = *reinterpret_cast<unsigned*>(&h1);
    o.z = *reinterpret_cast<unsigned*>(&h2); o.w = *reinterpret_cast<unsigned*>(&h3);
    *reinterpret_cast<uint4*>(d_Vh + i) = o;
}

// stage a 128x128 fp16 chunk (32KB) with XOR-16B swizzle, 8 chunks/thread
static __device__ __forceinline__ void stage_chunk(uint32_t kd, uint32_t vd,
                                                   const __half* kg, const __half* vg,
                                                   int tid) {
    #pragma unroll
    for (int t = 0; t < 8; ++t) {
        int idx = tid + t * NTHREADS;
        int r = idx >> 4, c16 = idx & 15;
        uint32_t dst = (uint32_t)(r * 256 + ((c16 ^ (r & 7)) << 4));
        cpa16(kd + dst, kg + (size_t)r * KSTRIDE + c16 * 8);
        cpa16(vd + dst, vg + (size_t)r * KSTRIDE + c16 * 8);
    }
}

__global__ void __launch_bounds__(NTHREADS, 1)
fa_f16_v9(const float* __restrict__ Q, float* __restrict__ O)
{
    extern __shared__ char sm[];
    const uint32_t sb = smem_u32(sm);

    const int iq   = (int)gridDim.x - 1 - (int)blockIdx.x;   // longest first
    const int h    = blockIdx.y;
    const int g    = h >> 2;
    const int tid  = threadIdx.x;
    const int w    = tid >> 5;
    const int lane = tid & 31;
    const int gid  = lane >> 2;
    const int t4   = lane & 3;
    const int strip  = w * 16;
    const int qrow0  = iq * BR;
    const int row0   = qrow0 + strip + gid;
    const int row1   = row0 + 8;
    const int maxrow = qrow0 + strip + 15;

    // ldmatrix per-lane address pieces
    const int rin = lane & 7;
    const int khi = (lane >> 3) & 1;
    const int qhi = (lane >> 4) & 1;
    const uint32_t g1base = (uint32_t)((qhi * 8 + rin) * 256);
    const uint32_t g2base = (uint32_t)((khi * 8 + rin) * 256);

    // ---- stage chunk 0 ----
    stage_chunk(sb, sb + SM_V0, d_Kh + (size_t)g * 128, d_Vh + (size_t)g * 128, tid);
    CP_COMMIT();

    // ---- Q fragments in registers (fp16, pre-scaled by scale*log2(e)) ----
    unsigned aq[8][4];
    {
        const float* q0 = Q + (size_t)row0 * QSTRIDE + h * HEAD_DIM;
        const float* q1 = q0 + (size_t)8 * QSTRIDE;
        const float sc = (float)(0.08838834764831845 * 1.4426950408889634);
        #pragma unroll
        for (int kc = 0; kc < 8; ++kc) {
            int c = kc * 16 + 2 * t4;
            aq[kc][0] = packh2(q0[c] * sc,     q0[c + 1] * sc);
            aq[kc][1] = packh2(q1[c] * sc,     q1[c + 1] * sc);
            aq[kc][2] = packh2(q0[c + 8] * sc, q0[c + 9] * sc);
            aq[kc][3] = packh2(q1[c + 8] * sc, q1[c + 9] * sc);
        }
    }

    float m0 = -1e30f, m1 = -1e30f, l0 = 0.f, l1 = 0.f;
    float o[16][4];
    #pragma unroll
    for (int nt = 0; nt < 16; ++nt)
        o[nt][0] = o[nt][1] = o[nt][2] = o[nt][3] = 0.f;

    for (int c = 0; c <= iq; ++c) {
        if (c < iq) {
            uint32_t b = (uint32_t)((c + 1) & 1) * 32768u;
            stage_chunk(sb + b, sb + SM_V0 + b,
                        d_Kh + (size_t)(c + 1) * 128 * KSTRIDE + g * 128,
                        d_Vh + (size_t)(c + 1) * 128 * KSTRIDE + g * 128, tid);
            CP_COMMIT();
            CP_WAIT1();
        } else {
            CP_WAIT0();
        }
        __syncthreads();

        const uint32_t kbc = sb + (uint32_t)(c & 1) * 32768u;
        const uint32_t vbc = kbc + SM_V0;
        const bool diag = (c == iq);

        #pragma unroll
        for (int t = 0; t < 2; ++t) {
            const int j = 2 * c + t;
            const int d = maxrow - 64 * j;
            if (d < 0) continue;
            const uint32_t kb = kbc + (uint32_t)t * 16384u;
            const uint32_t vb = vbc + (uint32_t)t * 16384u;

            // ---- GEMM1: S = Q @ K^T ----
            float s[8][4];
            #pragma unroll
            for (int nt = 0; nt < 8; ++nt)
                s[nt][0] = s[nt][1] = s[nt][2] = s[nt][3] = 0.f;

            #pragma unroll
            for (int kc = 0; kc < 8; ++kc) {
                const int kch = kc * 2 + khi;
                #pragma unroll
                for (int ntp = 0; ntp < 4; ++ntp) {
                    if (16 * ntp <= d) {
                        unsigned b0, b1, b2, b3;
                        ldsm4(b0, b1, b2, b3,
                              kb + g1base + (uint32_t)(ntp * 4096) +
                              (uint32_t)(((kch ^ rin) & 15) << 4));
                        mma_f16(s[2 * ntp],     aq[kc], b0, b1);
                        mma_f16(s[2 * ntp + 1], aq[kc], b2, b3);
                    }
                }
            }

            // ---- mask + online softmax (log2 domain) ----
            float mx0 = -1e30f, mx1 = -1e30f;
            #pragma unroll
            for (int nt = 0; nt < 8; ++nt) {
                if (diag) {
                    int col = j * 64 + nt * 8 + 2 * t4;
                    if (col     > row0) s[nt][0] = -1e30f;
                    if (col + 1 > row0) s[nt][1] = -1e30f;
                    if (col     > row1) s[nt][2] = -1e30f;
                    if (col + 1 > row1) s[nt][3] = -1e30f;
                }
                mx0 = fmaxf(mx0, fmaxf(s[nt][0], s[nt][1]));
                mx1 = fmaxf(mx1, fmaxf(s[nt][2], s[nt][3]));
            }
            // packed half2 quad-max reduce (2 shuffles instead of 4)
            {
                __half2 hmx = __floats2half2_rn(mx0, mx1);
                unsigned u = *reinterpret_cast<unsigned*>(&hmx);
                unsigned v1s = __shfl_xor_sync(0xffffffffu, u, 1);
                hmx = __hmax2(hmx, *reinterpret_cast<__half2*>(&v1s));
                u = *reinterpret_cast<unsigned*>(&hmx);
                unsigned v2s = __shfl_xor_sync(0xffffffffu, u, 2);
                hmx = __hmax2(hmx, *reinterpret_cast<__half2*>(&v2s));
                mx0 = __low2float(hmx);
                mx1 = __high2float(hmx);
            }

            const float nm0 = fmaxf(m0, mx0);
            const float nm1 = fmaxf(m1, mx1);
            const float cf0 = ex2f(m0 - nm0);
            const float cf1 = ex2f(m1 - nm1);
            m0 = nm0; m1 = nm1;

            float rs0 = 0.f, rs1 = 0.f;
            #pragma unroll
            for (int nt = 0; nt < 8; ++nt) {
                float p0 = ex2f(s[nt][0] - m0);
                float p1 = ex2f(s[nt][1] - m0);
                float p2 = ex2f(s[nt][2] - m1);
                float p3 = ex2f(s[nt][3] - m1);
                rs0 += p0 + p1; rs1 += p2 + p3;
                s[nt][0] = p0; s[nt][1] = p1; s[nt][2] = p2; s[nt][3] = p3;
            }
            l0 = l0 * cf0 + rs0;      // per-thread partial; quad-reduced at end
            l1 = l1 * cf1 + rs1;

            // vote-skip rescale: cf==1 exactly when the running max didn't move
            if (!__all_sync(0xffffffffu, (cf0 == 1.f) && (cf1 == 1.f))) {
                #pragma unroll
                for (int nt = 0; nt < 16; ++nt) {
                    o[nt][0] *= cf0; o[nt][1] *= cf0;
                    o[nt][2] *= cf1; o[nt][3] *= cf1;
                }
            }

            // ---- GEMM2: O += P @ V ----
            #pragma unroll
            for (int kc2 = 0; kc2 < 4; ++kc2) {
                if (16 * kc2 <= d) {
                    unsigned a[4];
                    a[0] = packh2(s[2 * kc2][0],     s[2 * kc2][1]);
                    a[1] = packh2(s[2 * kc2][2],     s[2 * kc2][3]);
                    a[2] = packh2(s[2 * kc2 + 1][0], s[2 * kc2 + 1][1]);
                    a[3] = packh2(s[2 * kc2 + 1][2], s[2 * kc2 + 1][3]);
                    #pragma unroll
                    for (int ntp2 = 0; ntp2 < 8; ++ntp2) {
                        unsigned b0, b1, b2, b3;
                        ldsm4t(b0, b1, b2, b3,
                               vb + g2base + (uint32_t)(kc2 * 4096) +
                               (uint32_t)((((2 * ntp2 + qhi) ^ rin) & 15) << 4));
                        mma_f16(o[2 * ntp2],     a, b0, b1);
                        mma_f16(o[2 * ntp2 + 1], a, b2, b3);
                    }
                }
            }
        }
        __syncthreads();
    }

    // ---- epilogue: quad-reduce l, normalize, store ----
    l0 += __shfl_xor_sync(0xffffffffu, l0, 1);
    l0 += __shfl_xor_sync(0xffffffffu, l0, 2);
    l1 += __shfl_xor_sync(0xffffffffu, l1, 1);
    l1 += __shfl_xor_sync(0xffffffffu, l1, 2);
    const float inv0 = 1.f / l0;
    const float inv1 = 1.f / l1;
    float* ob0 = O + (size_t)row0 * QSTRIDE + h * HEAD_DIM + 2 * t4;
    float* ob1 = ob0 + (size_t)8 * QSTRIDE;
    #pragma unroll
    for (int nt = 0; nt < 16; ++nt) {
        float2 x0 = make_float2(o[nt][0] * inv0, o[nt][1] * inv0);
        float2 x1 = make_float2(o[nt][2] * inv1, o[nt][3] * inv1);
        *reinterpret_cast<float2*>(ob0 + nt * 8) = x0;
        *reinterpret_cast<float2*>(ob1 + nt * 8) = x1;
    }
}

extern "C" void kernel_launch(void* const* d_in, const int* in_sizes, int n_in,
                              void* d_out, int out_size)
{
    const float* Q = (const float*)d_in[0];
    const float* K = (const float*)d_in[1];
    const float* V = (const float*)d_in[2];
    float* O = (float*)d_out;

    cvt_kv<<<1024, 256>>>(K, V);

    cudaFuncSetAttribute(fa_f16_v9,
                         cudaFuncAttributeMaxDynamicSharedMemorySize, SMEM_BYTES);
    dim3 grid(2048 / BR, NUM_HEADS);
    fa_f16_v9<<<grid, NTHREADS, SMEM_BYTES>>>(Q, O);
}